// round 17
// baseline (speedup 1.0000x reference)
#include <cuda_runtime.h>
#include <cuda_bf16.h>

#define NJ 24
#define EPSF 1e-6f

__device__ __forceinline__ float sqrt_ap(float x) {
    float r; asm("sqrt.approx.f32 %0, %1;" : "=f"(r) : "f"(x)); return r;
}
__device__ __forceinline__ float rcp_ap(float x) {
    float r; asm("rcp.approx.f32 %0, %1;" : "=f"(r) : "f"(x)); return r;
}

// Per-joint constants: 9 float4 (36 unique floats):
// q0 {G00,G11,G22,2G01}  q1 {2G02,2G12,bn0,bn1}  q2 {bn2,cn,P00,P11}
// q3 {P22,2P01,2P02,2P12} q4 {bP0,bP1,bP2,cP}    q5 {lL0,lL1,lL2,eL}
// q6 {R00,R01,R02,R10}   q7 {R11,R12,R20,R21}    q8 {R22,tr0,tr1,tr2}
// n2(x)=xGx+bn.x+cn, P = a0'*n2form + Qform, L linear; outputs via T=Σw[R|tr].

__global__ __launch_bounds__(256, 4)     // force <=64 regs -> 4 CTAs/SM
void shCaster_kernel(const float* __restrict__ xyz,
                     const float* __restrict__ vdir,
                     const float* __restrict__ transforms,
                     const float* __restrict__ sh_feats,
                     const float* __restrict__ locs,
                     float* __restrict__ out,
                     int half, int n)
{
    __shared__ __align__(16) float4 S[NJ * 9];

    if (threadIdx.x < NJ) {
        const int j = threadIdx.x;
        const float C0c = 0.28209479177387814f;
        const float C1c = 0.4886025119029199f;
        const float Bc  = 1.0925484305920792f;
        const float Cc  = 0.31539156525252005f;
        const float Dc  = 0.5462742152960396f;

        float R[3][3], trv[3], e[3];
        #pragma unroll
        for (int r = 0; r < 3; ++r) {
            #pragma unroll
            for (int c = 0; c < 3; ++c) R[r][c] = transforms[j * 16 + r * 4 + c];
            trv[r] = transforms[j * 16 + r * 4 + 3];
        }
        #pragma unroll
        for (int i = 0; i < 3; ++i) e[i] = locs[j * 3 + i] - trv[i];

        float f[9];
        #pragma unroll
        for (int k = 0; k < 9; ++k) f[k] = sh_feats[j * 9 + k];

        float a0p = C0c * f[0] + 0.5f - Cc * f[6];
        float aL[3] = { -C1c * f[3], -C1c * f[1], C1c * f[2] };
        float a4 = Bc * f[4], a5 = -Bc * f[5], a7 = -Bc * f[7], a8 = Dc * f[8];
        float b6 = 3.0f * Cc * f[6];

        float H[3][3];
        H[0][0] = a8;  H[1][1] = -a8;  H[2][2] = b6;
        H[0][1] = H[1][0] = 0.5f * a4;
        H[1][2] = H[2][1] = 0.5f * a5;
        H[0][2] = H[2][0] = 0.5f * a7;

        float G[3][3], HR[3][3], M2[3][3], he[3];
        #pragma unroll
        for (int a = 0; a < 3; ++a)
            #pragma unroll
            for (int b = 0; b < 3; ++b) {
                float s = 0.f;
                #pragma unroll
                for (int i = 0; i < 3; ++i) s += R[i][a] * R[i][b];
                G[a][b] = s;
            }
        #pragma unroll
        for (int i = 0; i < 3; ++i) {
            #pragma unroll
            for (int c = 0; c < 3; ++c) {
                float s = 0.f;
                #pragma unroll
                for (int k = 0; k < 3; ++k) s += H[i][k] * R[k][c];
                HR[i][c] = s;
            }
            float sv = 0.f;
            #pragma unroll
            for (int k = 0; k < 3; ++k) sv += H[i][k] * e[k];
            he[i] = sv;
        }
        #pragma unroll
        for (int a = 0; a < 3; ++a)
            #pragma unroll
            for (int b = 0; b < 3; ++b) {
                float s = 0.f;
                #pragma unroll
                for (int i = 0; i < 3; ++i) s += R[i][a] * HR[i][b];
                M2[a][b] = s;
            }

        float bn[3], bQ[3], lL[3];
        #pragma unroll
        for (int a = 0; a < 3; ++a) {
            bn[a] = -2.f * (R[0][a] * e[0] + R[1][a] * e[1] + R[2][a] * e[2]);
            bQ[a] = -2.f * (he[0] * R[0][a] + he[1] * R[1][a] + he[2] * R[2][a]);
            lL[a] = -(aL[0] * R[0][a] + aL[1] * R[1][a] + aL[2] * R[2][a]);
        }
        float cn = e[0]*e[0] + e[1]*e[1] + e[2]*e[2];
        float cQ = e[0]*he[0] + e[1]*he[1] + e[2]*he[2];
        float eL = aL[0]*e[0] + aL[1]*e[1] + aL[2]*e[2];

        S[j*9+0] = make_float4(G[0][0], G[1][1], G[2][2], 2.f*G[0][1]);
        S[j*9+1] = make_float4(2.f*G[0][2], 2.f*G[1][2], bn[0], bn[1]);
        S[j*9+2] = make_float4(bn[2], cn,
                               a0p*G[0][0] + M2[0][0], a0p*G[1][1] + M2[1][1]);
        S[j*9+3] = make_float4(a0p*G[2][2] + M2[2][2],
                               2.f*(a0p*G[0][1] + M2[0][1]),
                               2.f*(a0p*G[0][2] + M2[0][2]),
                               2.f*(a0p*G[1][2] + M2[1][2]));
        S[j*9+4] = make_float4(a0p*bn[0] + bQ[0], a0p*bn[1] + bQ[1],
                               a0p*bn[2] + bQ[2], a0p*cn + cQ);
        S[j*9+5] = make_float4(lL[0], lL[1], lL[2], eL);
        S[j*9+6] = make_float4(R[0][0], R[0][1], R[0][2], R[1][0]);
        S[j*9+7] = make_float4(R[1][1], R[1][2], R[2][0], R[2][1]);
        S[j*9+8] = make_float4(R[2][2], trv[0], trv[1], trv[2]);
    }
    __syncthreads();

    int t = blockIdx.x * blockDim.x + threadIdx.x;
    if (t >= half) return;
    int i0 = t, i1 = t + half;

    const float xa = __ldg(&xyz[3*i0]), ya = __ldg(&xyz[3*i0+1]), za = __ldg(&xyz[3*i0+2]);
    const float xb = __ldg(&xyz[3*i1]), yb = __ldg(&xyz[3*i1+1]), zb = __ldg(&xyz[3*i1+2]);

    const float xxa = xa*xa, yya = ya*ya, zza = za*za;
    const float xya = xa*ya, xza = xa*za, yza = ya*za;
    const float xxb = xb*xb, yyb = yb*yb, zzb = zb*zb;
    const float xyb = xb*yb, xzb = xb*zb, yzb = yb*zb;

    float wsa = 0.f, wsb = 0.f;
    float a00=0.f,a01=0.f,a02=0.f,a03=0.f, a10=0.f,a11=0.f,a12=0.f,a13=0.f;
    float a20=0.f,a21=0.f,a22=0.f,a23=0.f;
    float b00=0.f,b01=0.f,b02=0.f,b03=0.f, b10=0.f,b11=0.f,b12=0.f,b13=0.f;
    float b20=0.f,b21=0.f,b22=0.f,b23=0.f;

#pragma unroll 1
    for (int j = 0; j < NJ; ++j) {
        const float4* q = &S[j * 9];
        // all LDS up front — latency overlapped with the form math below
        const float4 q0 = q[0], q1 = q[1], q2 = q[2];
        const float4 q3 = q[3], q4 = q[4], q5 = q[5];
        const float4 q6 = q[6], q7 = q[7], q8 = q[8];

        // n2 first (split chains), sqrt launched ASAP
        float n2aA = fmaf(q0.x,xxa, fmaf(q0.y,yya, fmaf(q0.z,zza, fmaf(q0.w,xya, q2.y))));
        float n2aB = fmaf(q1.x,xza, fmaf(q1.y,yza, fmaf(q1.z,xa, fmaf(q1.w,ya, q2.x*za))));
        float n2bA = fmaf(q0.x,xxb, fmaf(q0.y,yyb, fmaf(q0.z,zzb, fmaf(q0.w,xyb, q2.y))));
        float n2bB = fmaf(q1.x,xzb, fmaf(q1.y,yzb, fmaf(q1.z,xb, fmaf(q1.w,yb, q2.x*zb))));
        float n2a = fmaxf(n2aA + n2aB, 0.f);
        float n2b = fmaxf(n2bA + n2bB, 0.f);
        float sa = sqrt_ap(n2a);
        float sb = sqrt_ap(n2b);

        // P and L evaluated while sqrt is in flight (split chains)
        float PaA = fmaf(q2.z,xxa, fmaf(q2.w,yya, fmaf(q3.x,zza, fmaf(q3.y,xya, q4.w))));
        float PaB = fmaf(q3.z,xza, fmaf(q3.w,yza, fmaf(q4.x,xa, fmaf(q4.y,ya, q4.z*za))));
        float PbA = fmaf(q2.z,xxb, fmaf(q2.w,yyb, fmaf(q3.x,zzb, fmaf(q3.y,xyb, q4.w))));
        float PbB = fmaf(q3.z,xzb, fmaf(q3.w,yzb, fmaf(q4.x,xb, fmaf(q4.y,yb, q4.z*zb))));
        float Pa = PaA + PaB;
        float Pb = PbA + PbB;
        float La  = fmaf(q5.x,xa, fmaf(q5.y,ya, fmaf(q5.z,za, q5.w)));
        float Lb  = fmaf(q5.x,xb, fmaf(q5.y,yb, fmaf(q5.z,zb, q5.w)));

        float dena = fmaf(La, sa, Pa), denb = fmaf(Lb, sb, Pb);
        float tta = fmaf(La - n2a, sa, Pa), ttb = fmaf(Lb - n2b, sb, Pb);
        float wa = fmaxf(tta, 0.f) * rcp_ap(fmaxf(dena, 1e-30f));
        float wb = fmaxf(ttb, 0.f) * rcp_ap(fmaxf(denb, 1e-30f));

        wsa += wa;                      wsb += wb;
        a00 = fmaf(wa, q6.x, a00);      b00 = fmaf(wb, q6.x, b00);
        a01 = fmaf(wa, q6.y, a01);      b01 = fmaf(wb, q6.y, b01);
        a02 = fmaf(wa, q6.z, a02);      b02 = fmaf(wb, q6.z, b02);
        a10 = fmaf(wa, q6.w, a10);      b10 = fmaf(wb, q6.w, b10);
        a11 = fmaf(wa, q7.x, a11);      b11 = fmaf(wb, q7.x, b11);
        a12 = fmaf(wa, q7.y, a12);      b12 = fmaf(wb, q7.y, b12);
        a20 = fmaf(wa, q7.z, a20);      b20 = fmaf(wb, q7.z, b20);
        a21 = fmaf(wa, q7.w, a21);      b21 = fmaf(wb, q7.w, b21);
        a22 = fmaf(wa, q8.x, a22);      b22 = fmaf(wb, q8.x, b22);
        a03 = fmaf(wa, q8.y, a03);      b03 = fmaf(wb, q8.y, b03);
        a13 = fmaf(wa, q8.z, a13);      b13 = fmaf(wb, q8.z, b13);
        a23 = fmaf(wa, q8.w, a23);      b23 = fmaf(wb, q8.w, b23);
    }

    // ---- epilogue ----
    const float vxa = __ldg(&vdir[3*i0]), vya = __ldg(&vdir[3*i0+1]), vza = __ldg(&vdir[3*i0+2]);
    const float vxb = __ldg(&vdir[3*i1]), vyb = __ldg(&vdir[3*i1+1]), vzb = __ldg(&vdir[3*i1+2]);

    float* outv = out + (size_t)3 * n;

    if (wsa > EPSF) {
        float inv = rcp_ap(wsa);
        out[3*i0]   = fmaf(a00, xa, fmaf(a01, ya, fmaf(a02, za, a03))) * inv;
        out[3*i0+1] = fmaf(a10, xa, fmaf(a11, ya, fmaf(a12, za, a13))) * inv;
        out[3*i0+2] = fmaf(a20, xa, fmaf(a21, ya, fmaf(a22, za, a23))) * inv;
        outv[3*i0]   = fmaf(a00, vxa, fmaf(a01, vya, a02 * vza)) * inv;
        outv[3*i0+1] = fmaf(a10, vxa, fmaf(a11, vya, a12 * vza)) * inv;
        outv[3*i0+2] = fmaf(a20, vxa, fmaf(a21, vya, a22 * vza)) * inv;
    } else {
        out[3*i0] = xa;  out[3*i0+1] = ya;  out[3*i0+2] = za;
        outv[3*i0] = vxa; outv[3*i0+1] = vya; outv[3*i0+2] = vza;
    }
    if (wsb > EPSF) {
        float inv = rcp_ap(wsb);
        out[3*i1]   = fmaf(b00, xb, fmaf(b01, yb, fmaf(b02, zb, b03))) * inv;
        out[3*i1+1] = fmaf(b10, xb, fmaf(b11, yb, fmaf(b12, zb, b13))) * inv;
        out[3*i1+2] = fmaf(b20, xb, fmaf(b21, yb, fmaf(b22, zb, b23))) * inv;
        outv[3*i1]   = fmaf(b00, vxb, fmaf(b01, vyb, b02 * vzb)) * inv;
        outv[3*i1+1] = fmaf(b10, vxb, fmaf(b11, vyb, b12 * vzb)) * inv;
        outv[3*i1+2] = fmaf(b20, vxb, fmaf(b21, vyb, b22 * vzb)) * inv;
    } else {
        out[3*i1] = xb;  out[3*i1+1] = yb;  out[3*i1+2] = zb;
        outv[3*i1] = vxb; outv[3*i1+1] = vyb; outv[3*i1+2] = vzb;
    }
}

extern "C" void kernel_launch(void* const* d_in, const int* in_sizes, int n_in,
                              void* d_out, int out_size) {
    const float* xyz        = (const float*)d_in[0];
    const float* viewdirs   = (const float*)d_in[1];
    const float* transforms = (const float*)d_in[2];
    // d_in[3] = ray_valid — unused
    const float* sh_feats   = (const float*)d_in[4];
    const float* locs       = (const float*)d_in[5];
    float* out = (float*)d_out;

    int n = in_sizes[0] / 3;      // 524288
    int half = n / 2;             // 262144
    int threads = 256;
    int blocks = (half + threads - 1) / threads;
    shCaster_kernel<<<blocks, threads>>>(xyz, viewdirs, transforms, sh_feats,
                                         locs, out, half, n);
}